// round 1
// baseline (speedup 1.0000x reference)
#include <cuda_runtime.h>

#define D 128
#define NMAX 100000

// Scratch: h_src = g_h[0], h_dst = g_h[1]  (node-level precomputed hidden states)
__device__ float g_h[2][(size_t)NMAX * D];
__device__ int g_idx64;   // 1 if src/dst indices are int64, 0 if int32

// ---------------------------------------------------------------------------
// Detect index dtype: if the first 16 values interpreted as int64 are all in
// [0, N), the data is int64 (little-endian int32 pairs would be ~2^32-scale).
// ---------------------------------------------------------------------------
__global__ void detect_idx_kernel(const long long* __restrict__ p, int N) {
    int ok = 0;
#pragma unroll
    for (int i = 0; i < 16; i++) {
        long long v = p[i];
        if (v >= 0 && v < (long long)N) ok++;
    }
    g_idx64 = (ok >= 12) ? 1 : 0;
}

// ---------------------------------------------------------------------------
// Node GEMM: out[n, j] = sum_k x[n, k] * W[j, k] + b[j]
// (h = x @ W^T + b).  BM=128 rows/block, BN=128 (all cols), BK=8.
// 256 threads, 8x8 register tile per thread.
// ---------------------------------------------------------------------------
__global__ __launch_bounds__(256) void node_gemm_kernel(
    const float* __restrict__ x, const float* __restrict__ W,
    const float* __restrict__ b, int which, int N)
{
    __shared__ float As[8][128];   // [k][row]
    __shared__ float Bs[8][128];   // [k][col j]

    float* __restrict__ out = g_h[which];

    const int tid = threadIdx.x;
    const int tx = tid & 15;          // col group (j = tx*8 .. tx*8+7)
    const int ty = tid >> 4;          // row group (r = ty*8 .. ty*8+7)
    const int row0 = blockIdx.x * 128;

    float acc[8][8];
#pragma unroll
    for (int i = 0; i < 8; i++)
#pragma unroll
        for (int j = 0; j < 8; j++) acc[i][j] = 0.0f;

    const int lr = tid >> 1;          // 0..127 : row within tile / W row j
    const int lh = (tid & 1) * 4;     // 0 or 4 : k-offset of float4

    for (int kt = 0; kt < 128; kt += 8) {
        float4 av = make_float4(0.f, 0.f, 0.f, 0.f);
        const int grow = row0 + lr;
        if (grow < N)
            av = *(const float4*)(x + (size_t)grow * D + kt + lh);
        const float4 bv = *(const float4*)(W + (size_t)lr * D + kt + lh);

        As[lh + 0][lr] = av.x; As[lh + 1][lr] = av.y;
        As[lh + 2][lr] = av.z; As[lh + 3][lr] = av.w;
        Bs[lh + 0][lr] = bv.x; Bs[lh + 1][lr] = bv.y;
        Bs[lh + 2][lr] = bv.z; Bs[lh + 3][lr] = bv.w;
        __syncthreads();

#pragma unroll
        for (int k = 0; k < 8; k++) {
            float a[8], bb[8];
#pragma unroll
            for (int i = 0; i < 8; i++) a[i]  = As[k][ty * 8 + i];
#pragma unroll
            for (int j = 0; j < 8; j++) bb[j] = Bs[k][tx * 8 + j];
#pragma unroll
            for (int i = 0; i < 8; i++)
#pragma unroll
                for (int j = 0; j < 8; j++)
                    acc[i][j] = fmaf(a[i], bb[j], acc[i][j]);
        }
        __syncthreads();
    }

    const float4 b0 = *(const float4*)(b + tx * 8);
    const float4 b1 = *(const float4*)(b + tx * 8 + 4);

#pragma unroll
    for (int i = 0; i < 8; i++) {
        const int grow = row0 + ty * 8 + i;
        if (grow < N) {
            float4 o0 = make_float4(acc[i][0] + b0.x, acc[i][1] + b0.y,
                                    acc[i][2] + b0.z, acc[i][3] + b0.w);
            float4 o1 = make_float4(acc[i][4] + b1.x, acc[i][5] + b1.y,
                                    acc[i][6] + b1.z, acc[i][7] + b1.w);
            *(float4*)(out + (size_t)grow * D + tx * 8)     = o0;
            *(float4*)(out + (size_t)grow * D + tx * 8 + 4) = o1;
        }
    }
}

// ---------------------------------------------------------------------------
// Edge pass: warp-per-edge.
//   v = relu(h_src[src[e]] + h_dst[dst[e]])   -> embs[e, :]
//   score[e, c] = dot(v, W_out[c]) + b_out[c]  (C = 2)
// ---------------------------------------------------------------------------
__global__ __launch_bounds__(256) void edge_kernel(
    const void* __restrict__ srcp, const void* __restrict__ dstp,
    const float* __restrict__ W_out, const float* __restrict__ b_out,
    float* __restrict__ score, float* __restrict__ embs,
    long long E, int N)
{
    __shared__ float4 w0s[32];
    __shared__ float4 w1s[32];
    __shared__ float2 sc[8];

    const int tid = threadIdx.x;
    if (tid < 64) {
        float4 w = ((const float4*)W_out)[tid];
        if (tid < 32) w0s[tid] = w; else w1s[tid - 32] = w;
    }
    __syncthreads();

    const int warp = tid >> 5;
    const int lane = tid & 31;
    const long long e = (long long)blockIdx.x * 8 + warp;
    const float* __restrict__ hs = g_h[0];
    const float* __restrict__ hd = g_h[1];

    if (e < E) {
        int s, d;
        if (g_idx64) {
            s = (int)((const long long*)srcp)[e];
            d = (int)((const long long*)dstp)[e];
        } else {
            s = ((const int*)srcp)[e];
            d = ((const int*)dstp)[e];
        }
        s = min(max(s, 0), N - 1);
        d = min(max(d, 0), N - 1);

        const float4 a  = ((const float4*)hs)[(size_t)s * 32 + lane];
        const float4 bb = ((const float4*)hd)[(size_t)d * 32 + lane];
        float4 v;
        v.x = fmaxf(a.x + bb.x, 0.0f);
        v.y = fmaxf(a.y + bb.y, 0.0f);
        v.z = fmaxf(a.z + bb.z, 0.0f);
        v.w = fmaxf(a.w + bb.w, 0.0f);

        ((float4*)embs)[(size_t)e * 32 + lane] = v;

        const float4 w0 = w0s[lane];
        const float4 w1 = w1s[lane];
        float d0 = v.x * w0.x + v.y * w0.y + v.z * w0.z + v.w * w0.w;
        float d1 = v.x * w1.x + v.y * w1.y + v.z * w1.z + v.w * w1.w;
#pragma unroll
        for (int o = 16; o > 0; o >>= 1) {
            d0 += __shfl_xor_sync(0xffffffffu, d0, o);
            d1 += __shfl_xor_sync(0xffffffffu, d1, o);
        }
        if (lane == 0)
            sc[warp] = make_float2(d0 + b_out[0], d1 + b_out[1]);
    }
    __syncthreads();

    // Coalesced score store: 8 edges * float2 = 64B per block.
    const long long base = (long long)blockIdx.x * 8;
    if (tid < 8 && base + tid < E)
        ((float2*)score)[base + tid] = sc[tid];
}

// ---------------------------------------------------------------------------
// kernel_launch
// Inputs (metadata order): x, src, dst, W_src, b_src, W_dst, b_dst, W_out, b_out
// Output: concat(score [E,2], edge_embs [E,128]) as float32.
// ---------------------------------------------------------------------------
extern "C" void kernel_launch(void* const* d_in, const int* in_sizes, int n_in,
                              void* d_out, int out_size)
{
    const float* x     = (const float*)d_in[0];
    const void*  src   = d_in[1];
    const void*  dst   = d_in[2];
    const float* W_src = (const float*)d_in[3];
    const float* b_src = (const float*)d_in[4];
    const float* W_dst = (const float*)d_in[5];
    const float* b_dst = (const float*)d_in[6];
    const float* W_out = (const float*)d_in[7];
    const float* b_out = (const float*)d_in[8];

    const int N = in_sizes[0] / D;
    const long long E = in_sizes[1];

    float* out   = (float*)d_out;
    float* score = out;                       // [E, 2]
    float* embs  = out + (size_t)E * 2;       // [E, 128]

    detect_idx_kernel<<<1, 1>>>((const long long*)src, N);

    const int gb = (N + 127) / 128;
    node_gemm_kernel<<<gb, 256>>>(x, W_src, b_src, 0, N);
    node_gemm_kernel<<<gb, 256>>>(x, W_dst, b_dst, 1, N);

    const int eb = (int)((E + 7) / 8);
    edge_kernel<<<eb, 256>>>(src, dst, W_out, b_out, score, embs, E, N);
}

// round 2
// speedup vs baseline: 1.0051x; 1.0051x over previous
#include <cuda_runtime.h>

#define D 128
#define NMAX 100000

// Scratch: h_src = g_h[0], h_dst = g_h[1]
__device__ float g_h[2][(size_t)NMAX * D];
__device__ int g_idx64;

__global__ void detect_idx_kernel(const long long* __restrict__ p, int N) {
    int ok = 0;
#pragma unroll
    for (int i = 0; i < 16; i++) {
        long long v = p[i];
        if (v >= 0 && v < (long long)N) ok++;
    }
    g_idx64 = (ok >= 12) ? 1 : 0;
}

// ---------------------------------------------------------------------------
// Node GEMM: out[n, j] = sum_k x[n, k] * W[j, k] + b[j]
// 128x128 tile, BK=8, 256 threads, 8x8 per-thread tile.
// Shared reads via float4 (LDS.128) -> conflict-free (each 8-lane phase
// covers 32 distinct banks).
// ---------------------------------------------------------------------------
__global__ __launch_bounds__(256) void node_gemm_kernel(
    const float* __restrict__ x, const float* __restrict__ W,
    const float* __restrict__ b, int which, int N)
{
    __shared__ float As[8][128];   // [k][row]
    __shared__ float Bs[8][128];   // [k][col]

    float* __restrict__ out = g_h[which];

    const int tid = threadIdx.x;
    const int tx = tid & 15;          // col group
    const int ty = tid >> 4;          // row group
    const int row0 = blockIdx.x * 128;

    float acc[8][8];
#pragma unroll
    for (int i = 0; i < 8; i++)
#pragma unroll
        for (int j = 0; j < 8; j++) acc[i][j] = 0.0f;

    const int lr = tid >> 1;
    const int lh = (tid & 1) * 4;

    for (int kt = 0; kt < 128; kt += 8) {
        float4 av = make_float4(0.f, 0.f, 0.f, 0.f);
        const int grow = row0 + lr;
        if (grow < N)
            av = *(const float4*)(x + (size_t)grow * D + kt + lh);
        const float4 bv = *(const float4*)(W + (size_t)lr * D + kt + lh);

        As[lh + 0][lr] = av.x; As[lh + 1][lr] = av.y;
        As[lh + 2][lr] = av.z; As[lh + 3][lr] = av.w;
        Bs[lh + 0][lr] = bv.x; Bs[lh + 1][lr] = bv.y;
        Bs[lh + 2][lr] = bv.z; Bs[lh + 3][lr] = bv.w;
        __syncthreads();

#pragma unroll
        for (int k = 0; k < 8; k++) {
            // Vectorized shared loads: LDS.128, conflict-free.
            const float4 a0 = ((const float4*)&As[k][0])[ty * 2 + 0];
            const float4 a1 = ((const float4*)&As[k][0])[ty * 2 + 1];
            const float4 b0 = ((const float4*)&Bs[k][0])[tx * 2 + 0];
            const float4 b1 = ((const float4*)&Bs[k][0])[tx * 2 + 1];
            float a[8] = {a0.x, a0.y, a0.z, a0.w, a1.x, a1.y, a1.z, a1.w};
            float bb[8] = {b0.x, b0.y, b0.z, b0.w, b1.x, b1.y, b1.z, b1.w};
#pragma unroll
            for (int i = 0; i < 8; i++)
#pragma unroll
                for (int j = 0; j < 8; j++)
                    acc[i][j] = fmaf(a[i], bb[j], acc[i][j]);
        }
        __syncthreads();
    }

    const float4 bv0 = *(const float4*)(b + tx * 8);
    const float4 bv1 = *(const float4*)(b + tx * 8 + 4);

#pragma unroll
    for (int i = 0; i < 8; i++) {
        const int grow = row0 + ty * 8 + i;
        if (grow < N) {
            float4 o0 = make_float4(acc[i][0] + bv0.x, acc[i][1] + bv0.y,
                                    acc[i][2] + bv0.z, acc[i][3] + bv0.w);
            float4 o1 = make_float4(acc[i][4] + bv1.x, acc[i][5] + bv1.y,
                                    acc[i][6] + bv1.z, acc[i][7] + bv1.w);
            *(float4*)(out + (size_t)grow * D + tx * 8)     = o0;
            *(float4*)(out + (size_t)grow * D + tx * 8 + 4) = o1;
        }
    }
}

// ---------------------------------------------------------------------------
// Edge pass: warp-per-edge. Streaming stores (__stcs) for outputs keep the
// 102MB h arrays resident in L2 for the gathers.
// ---------------------------------------------------------------------------
__global__ __launch_bounds__(256) void edge_kernel(
    const void* __restrict__ srcp, const void* __restrict__ dstp,
    const float* __restrict__ W_out, const float* __restrict__ b_out,
    float* __restrict__ score, float* __restrict__ embs,
    long long E, int N)
{
    __shared__ float4 w0s[32];
    __shared__ float4 w1s[32];
    __shared__ float2 sc[8];

    const int tid = threadIdx.x;
    if (tid < 64) {
        float4 w = ((const float4*)W_out)[tid];
        if (tid < 32) w0s[tid] = w; else w1s[tid - 32] = w;
    }
    __syncthreads();

    const int warp = tid >> 5;
    const int lane = tid & 31;
    const long long e = (long long)blockIdx.x * 8 + warp;
    const float* __restrict__ hs = g_h[0];
    const float* __restrict__ hd = g_h[1];

    if (e < E) {
        int s, d;
        if (g_idx64) {
            s = (int)__ldcs(&((const long long*)srcp)[e]);
            d = (int)__ldcs(&((const long long*)dstp)[e]);
        } else {
            s = __ldcs(&((const int*)srcp)[e]);
            d = __ldcs(&((const int*)dstp)[e]);
        }
        s = min(max(s, 0), N - 1);
        d = min(max(d, 0), N - 1);

        const float4 a  = ((const float4*)hs)[(size_t)s * 32 + lane];
        const float4 bb = ((const float4*)hd)[(size_t)d * 32 + lane];
        float4 v;
        v.x = fmaxf(a.x + bb.x, 0.0f);
        v.y = fmaxf(a.y + bb.y, 0.0f);
        v.z = fmaxf(a.z + bb.z, 0.0f);
        v.w = fmaxf(a.w + bb.w, 0.0f);

        // Streaming store: bypass L2 allocation for the 819MB output.
        __stcs(&((float4*)embs)[(size_t)e * 32 + lane], v);

        const float4 w0 = w0s[lane];
        const float4 w1 = w1s[lane];
        float d0 = v.x * w0.x + v.y * w0.y + v.z * w0.z + v.w * w0.w;
        float d1 = v.x * w1.x + v.y * w1.y + v.z * w1.z + v.w * w1.w;
#pragma unroll
        for (int o = 16; o > 0; o >>= 1) {
            d0 += __shfl_xor_sync(0xffffffffu, d0, o);
            d1 += __shfl_xor_sync(0xffffffffu, d1, o);
        }
        if (lane == 0)
            sc[warp] = make_float2(d0 + b_out[0], d1 + b_out[1]);
    }
    __syncthreads();

    const long long base = (long long)blockIdx.x * 8;
    if (tid < 8 && base + tid < E)
        __stcs(&((float2*)score)[base + tid], sc[tid]);
}

extern "C" void kernel_launch(void* const* d_in, const int* in_sizes, int n_in,
                              void* d_out, int out_size)
{
    const float* x     = (const float*)d_in[0];
    const void*  src   = d_in[1];
    const void*  dst   = d_in[2];
    const float* W_src = (const float*)d_in[3];
    const float* b_src = (const float*)d_in[4];
    const float* W_dst = (const float*)d_in[5];
    const float* b_dst = (const float*)d_in[6];
    const float* W_out = (const float*)d_in[7];
    const float* b_out = (const float*)d_in[8];

    const int N = in_sizes[0] / D;
    const long long E = in_sizes[1];

    float* out   = (float*)d_out;
    float* score = out;                       // [E, 2]
    float* embs  = out + (size_t)E * 2;       // [E, 128]

    detect_idx_kernel<<<1, 1>>>((const long long*)src, N);

    const int gb = (N + 127) / 128;
    node_gemm_kernel<<<gb, 256>>>(x, W_src, b_src, 0, N);
    node_gemm_kernel<<<gb, 256>>>(x, W_dst, b_dst, 1, N);

    const int eb = (int)((E + 7) / 8);
    edge_kernel<<<eb, 256>>>(src, dst, W_out, b_out, score, embs, E, N);
}